// round 16
// baseline (speedup 1.0000x reference)
#include <cuda_runtime.h>
#include <cuda_bf16.h>
#include <cuda_fp16.h>
#include <math.h>
#include <stdint.h>

// ---------------------------------------------------------------------------
// Static device scratch (no allocations allowed anywhere).
// Instance: N=50000, E=800000 (+N self loops), Fin=128, H=4, C=64.
// ---------------------------------------------------------------------------
#define NMAX 65536
#define EMAX 2200000

__device__ __half g_h1[(size_t)NMAX * 256];        // layer-1 features (fp16)
__device__ __half g_h2[(size_t)NMAX * 64];         // layer-2 features (fp16)
__device__ __nv_bfloat16 g_x2h[(size_t)NMAX * 256];// relu(agg1+b1) split hi
__device__ __nv_bfloat16 g_x2l[(size_t)NMAX * 256];// relu(agg1+b1) split lo
__device__ __nv_bfloat16 g_w1h[128 * 256], g_w1l[128 * 256];
__device__ __nv_bfloat16 g_w2h[256 * 64],  g_w2l[256 * 64];
__device__ float g_as1[NMAX * 4];
__device__ float g_ad1[NMAX * 4];
__device__ float g_as2[NMAX];
__device__ float g_ad2[NMAX];
__device__ int   g_deg[NMAX];
__device__ int   g_pos[NMAX];
__device__ int   g_rowptr[NMAX + 1];
__device__ int   g_esrc[EMAX];

// ---------------------------------------------------------------------------
// CSR construction (counting sort by destination). edge_index is INT32.
// ---------------------------------------------------------------------------
__global__ void zero_deg_kernel(int Nn) {
    int i = blockIdx.x * blockDim.x + threadIdx.x;
    if (i < Nn) g_deg[i] = 0;
}

__global__ void count_kernel(const int* __restrict__ ei, int E, int Nn) {
    int i = blockIdx.x * blockDim.x + threadIdx.x;
    int tot = E + Nn;
    if (i >= tot) return;
    int d = (i < E) ? ei[E + i] : (i - E);
    if ((unsigned)d < (unsigned)Nn) atomicAdd(&g_deg[d], 1);
}

__global__ void scan_kernel(int N) {
    __shared__ int ssum[1024];
    int tid = threadIdx.x;
    int chunk = (N + 1023) >> 10;
    int start = tid * chunk;
    int end = min(start + chunk, N);
    int s = 0;
    for (int i = start; i < end; i++) s += g_deg[i];
    ssum[tid] = s;
    __syncthreads();
    for (int off = 1; off < 1024; off <<= 1) {
        int v = (tid >= off) ? ssum[tid - off] : 0;
        __syncthreads();
        ssum[tid] += v;
        __syncthreads();
    }
    int run = (tid > 0) ? ssum[tid - 1] : 0;
    for (int i = start; i < end; i++) {
        g_rowptr[i] = run;
        g_pos[i] = run;
        run += g_deg[i];
    }
    if (start < N && end == N) g_rowptr[N] = run;
}

__global__ void fill_kernel(const int* __restrict__ ei, int E, int Nn) {
    int i = blockIdx.x * blockDim.x + threadIdx.x;
    int tot = E + Nn;
    if (i >= tot) return;
    int s, d;
    if (i < E) { s = ei[i]; d = ei[E + i]; }
    else       { s = d = i - E; }
    if ((unsigned)d >= (unsigned)Nn || (unsigned)s >= (unsigned)Nn) return;
    int slot = atomicAdd(&g_pos[d], 1);
    g_esrc[slot] = s;
}

// ---------------------------------------------------------------------------
// fp32 -> (bf16 hi, bf16 lo) split for the WEIGHTS only (x is split inside
// sgemm1's staging now). 36K elements -> ~1us.
// ---------------------------------------------------------------------------
__global__ void splitw_kernel(const float* __restrict__ W1,
                              const float* __restrict__ W2) {
    const int NW1 = 128 * 256, NW2 = 256 * 64;
    int total4 = (NW1 + NW2) >> 2;
    for (int i = blockIdx.x * blockDim.x + threadIdx.x; i < total4;
         i += gridDim.x * blockDim.x) {
        int base = i << 2;
        const float* src;
        __nv_bfloat16 *dh, *dl;
        if (base < NW1) { src = W1 + base;      dh = g_w1h + base;      dl = g_w1l + base; }
        else            { int o = base - NW1;   src = W2 + o; dh = g_w2h + o; dl = g_w2l + o; }
        float4 v = *reinterpret_cast<const float4*>(src);
        __nv_bfloat16 h0 = __float2bfloat16(v.x), h1 = __float2bfloat16(v.y);
        __nv_bfloat16 h2 = __float2bfloat16(v.z), h3 = __float2bfloat16(v.w);
        __nv_bfloat162 hh0 = __halves2bfloat162(h0, h1);
        __nv_bfloat162 hh1 = __halves2bfloat162(h2, h3);
        __nv_bfloat162 ll0 = __floats2bfloat162_rn(v.x - __bfloat162float(h0),
                                                   v.y - __bfloat162float(h1));
        __nv_bfloat162 ll1 = __floats2bfloat162_rn(v.z - __bfloat162float(h2),
                                                   v.w - __bfloat162float(h3));
        uint2 uh, ul;
        uh.x = *reinterpret_cast<uint32_t*>(&hh0);
        uh.y = *reinterpret_cast<uint32_t*>(&hh1);
        ul.x = *reinterpret_cast<uint32_t*>(&ll0);
        ul.y = *reinterpret_cast<uint32_t*>(&ll1);
        *reinterpret_cast<uint2*>(dh) = uh;
        *reinterpret_cast<uint2*>(dl) = ul;
    }
}

// ---------------------------------------------------------------------------
// bf16 tensor-core GEMM (3-term split), fp16 output, fused alpha epilogue.
// ASPLIT=1: A given as fp32, fetched via LDG-prefetch and split to bf16 hi/lo
//           during smem staging (saves the standalone x-split pass).
// ASPLIT=0: A given as pre-split bf16 hi/lo, staged via cp.async.
// AMODE=1 (GEMM1): warp's 64-col span = one head -> direct alpha store.
// AMODE=2 (GEMM2, H=1): two column-warps combine via smem.
// ---------------------------------------------------------------------------
__device__ __forceinline__ void ldsm_x4(uint32_t r[4], uint32_t addr) {
    asm volatile("ldmatrix.sync.aligned.m8n8.x4.shared.b16 {%0,%1,%2,%3}, [%4];"
                 : "=r"(r[0]), "=r"(r[1]), "=r"(r[2]), "=r"(r[3]) : "r"(addr));
}
__device__ __forceinline__ void ldsm_x4_t(uint32_t r[4], uint32_t addr) {
    asm volatile("ldmatrix.sync.aligned.m8n8.x4.trans.shared.b16 {%0,%1,%2,%3}, [%4];"
                 : "=r"(r[0]), "=r"(r[1]), "=r"(r[2]), "=r"(r[3]) : "r"(addr));
}
__device__ __forceinline__ void mma_bf16(float c[4], const uint32_t a[4],
                                         uint32_t b0, uint32_t b1) {
    asm volatile(
        "mma.sync.aligned.m16n8k16.row.col.f32.bf16.bf16.f32 "
        "{%0,%1,%2,%3}, {%4,%5,%6,%7}, {%8,%9}, {%0,%1,%2,%3};\n"
        : "+f"(c[0]), "+f"(c[1]), "+f"(c[2]), "+f"(c[3])
        : "r"(a[0]), "r"(a[1]), "r"(a[2]), "r"(a[3]), "r"(b0), "r"(b1));
}
__device__ __forceinline__ void cp16(uint32_t dst, const void* src, int sz) {
    asm volatile("cp.async.cg.shared.global [%0], [%1], 16, %2;"
                 :: "r"(dst), "l"(src), "r"(sz));
}
#define CP_COMMIT() asm volatile("cp.async.commit_group;" ::: "memory")
#define CP_WAIT0()  asm volatile("cp.async.wait_group 0;" ::: "memory")

template <int BN, int WN, int AMODE, int ASPLIT>
__device__ __forceinline__ void mma_gemm_body(const void* __restrict__ Ah_,
                                              const __nv_bfloat16* __restrict__ Al,
                                              const __nv_bfloat16* __restrict__ Bh,
                                              const __nv_bfloat16* __restrict__ Bl,
                                              __half* __restrict__ C,
                                              const float* __restrict__ asrc,
                                              const float* __restrict__ adst,
                                              float* __restrict__ as_out,
                                              float* __restrict__ ad_out,
                                              int M, int N, int K) {
    constexpr int BM  = 128;
    constexpr int NIC = BN / 8;
    constexpr int NP  = WN / 16;
    constexpr int NBLK = WN / 8;

    __shared__ uint4 sAh[2][256], sAl[2][256];
    __shared__ uint4 sBh[2][BN * 2], sBl[2][BN * 2];
    __shared__ float sAS[BM][2], sAD[BM][2];   // AMODE==2 combine buffer

    const int tid    = threadIdx.x;
    const int warpId = tid >> 5;
    const int lane   = tid & 31;
    const int row0 = blockIdx.y * BM;
    const int col0 = blockIdx.x * BN;

    const int aki = tid >> 7, ami = (tid >> 3) & 15, arow = tid & 7;
    const int aRowG = row0 + ami * 8 + arow;
    const int aDst  = (ami * 2 + aki) * 8 + arow;
    const bool aIn  = (aRowG < M);
    const int aszv  = aIn ? 16 : 0;

    const bool bAct = (tid < BN * 2);
    const int bki  = tid / (NIC * 8);
    const int brem = tid % (NIC * 8);
    const int bni  = brem >> 3, brow = brem & 7;
    const int bDst = (bni * 2 + bki) * 8 + brow;
    const int bColG = col0 + bni * 8;

    uint32_t baseAh[2] = {(uint32_t)__cvta_generic_to_shared(&sAh[0][0]),
                          (uint32_t)__cvta_generic_to_shared(&sAh[1][0])};
    uint32_t baseAl[2] = {(uint32_t)__cvta_generic_to_shared(&sAl[0][0]),
                          (uint32_t)__cvta_generic_to_shared(&sAl[1][0])};
    uint32_t baseBh[2] = {(uint32_t)__cvta_generic_to_shared(&sBh[0][0]),
                          (uint32_t)__cvta_generic_to_shared(&sBh[1][0])};
    uint32_t baseBl[2] = {(uint32_t)__cvta_generic_to_shared(&sBl[0][0]),
                          (uint32_t)__cvta_generic_to_shared(&sBl[1][0])};

    // ---- producers ----
    float4 aF[2];                  // ASPLIT: fp32 A prefetch (8 floats)
    auto fetchA = [&](int k0) {
        if constexpr (ASPLIT) {
            const float* Af = (const float*)Ah_;
            if (aIn) {
                const float* p = Af + (size_t)aRowG * K + k0 + aki * 8;
                aF[0] = *reinterpret_cast<const float4*>(p);
                aF[1] = *reinterpret_cast<const float4*>(p + 4);
            } else {
                aF[0] = aF[1] = make_float4(0.f, 0.f, 0.f, 0.f);
            }
        }
    };
    auto stageA = [&](int buf) {   // ASPLIT only: convert regs -> smem hi/lo
        if constexpr (ASPLIT) {
            float v[8] = {aF[0].x, aF[0].y, aF[0].z, aF[0].w,
                          aF[1].x, aF[1].y, aF[1].z, aF[1].w};
            __nv_bfloat16 hb[8];
            float lf[8];
#pragma unroll
            for (int e = 0; e < 8; e++) {
                hb[e] = __float2bfloat16(v[e]);
                lf[e] = v[e] - __bfloat162float(hb[e]);
            }
            uint4 uh, ul;
            {
                __nv_bfloat162 p0 = __halves2bfloat162(hb[0], hb[1]);
                __nv_bfloat162 p1 = __halves2bfloat162(hb[2], hb[3]);
                __nv_bfloat162 p2 = __halves2bfloat162(hb[4], hb[5]);
                __nv_bfloat162 p3 = __halves2bfloat162(hb[6], hb[7]);
                uh.x = *reinterpret_cast<uint32_t*>(&p0);
                uh.y = *reinterpret_cast<uint32_t*>(&p1);
                uh.z = *reinterpret_cast<uint32_t*>(&p2);
                uh.w = *reinterpret_cast<uint32_t*>(&p3);
            }
            {
                __nv_bfloat162 p0 = __floats2bfloat162_rn(lf[0], lf[1]);
                __nv_bfloat162 p1 = __floats2bfloat162_rn(lf[2], lf[3]);
                __nv_bfloat162 p2 = __floats2bfloat162_rn(lf[4], lf[5]);
                __nv_bfloat162 p3 = __floats2bfloat162_rn(lf[6], lf[7]);
                ul.x = *reinterpret_cast<uint32_t*>(&p0);
                ul.y = *reinterpret_cast<uint32_t*>(&p1);
                ul.z = *reinterpret_cast<uint32_t*>(&p2);
                ul.w = *reinterpret_cast<uint32_t*>(&p3);
            }
            sAh[buf][aDst] = uh;
            sAl[buf][aDst] = ul;
        }
    };
    auto loadTileAsync = [&](int k0, int buf) {   // cp.async parts (B, and A if !ASPLIT)
        if constexpr (!ASPLIT) {
            const __nv_bfloat16* Ahb = (const __nv_bfloat16*)Ah_;
            cp16(baseAh[buf] + aDst * 16, Ahb + (size_t)aRowG * K + k0 + aki * 8, aszv);
            cp16(baseAl[buf] + aDst * 16, Al + (size_t)aRowG * K + k0 + aki * 8, aszv);
        }
        if (bAct) {
            int kk = k0 + bki * 8 + brow;
            cp16(baseBh[buf] + bDst * 16, Bh + (size_t)kk * N + bColG, 16);
            cp16(baseBl[buf] + bDst * 16, Bl + (size_t)kk * N + bColG, 16);
        }
        CP_COMMIT();
    };

    // ---- consumer mapping ----
    const int wm = warpId & 3;
    const int wn = warpId >> 2;
    const int mi0 = wm * 4;
    const int ni0 = wn * (WN / 8);
    const int q = lane >> 3, r8 = lane & 7;
    uint32_t aoff[2], boff[NP];
#pragma unroll
    for (int mt = 0; mt < 2; mt++)
        aoff[mt] = ((mi0 + mt * 2 + (q & 1)) * 2 + (q >> 1)) * 128 + r8 * 16;
#pragma unroll
    for (int np = 0; np < NP; np++)
        boff[np] = ((ni0 + np * 2 + (q >> 1)) * 2 + (q & 1)) * 128 + r8 * 16;

    float acc[2][NBLK][4];
#pragma unroll
    for (int mt = 0; mt < 2; mt++)
#pragma unroll
        for (int nb = 0; nb < NBLK; nb++)
#pragma unroll
            for (int e = 0; e < 4; e++) acc[mt][nb][e] = 0.f;

    const int KT = K >> 4;
    fetchA(0);
    loadTileAsync(0, 0);
    stageA(0);
    int buf = 0;
    for (int t = 0; t < KT; t++) {
        CP_WAIT0();
        __syncthreads();
        if (t + 1 < KT) {
            fetchA((t + 1) << 4);                 // LDG issues; hidden by mma
            loadTileAsync((t + 1) << 4, buf ^ 1);
        }

        uint32_t ah[2][4], al[2][4];
#pragma unroll
        for (int mt = 0; mt < 2; mt++) {
            ldsm_x4(ah[mt], baseAh[buf] + aoff[mt]);
            ldsm_x4(al[mt], baseAl[buf] + aoff[mt]);
        }
#pragma unroll
        for (int np = 0; np < NP; np++) {
            uint32_t bh[4], bl[4];
            ldsm_x4_t(bh, baseBh[buf] + boff[np]);
            ldsm_x4_t(bl, baseBl[buf] + boff[np]);
#pragma unroll
            for (int mt = 0; mt < 2; mt++)
#pragma unroll
                for (int s = 0; s < 2; s++) {
                    int nb = np * 2 + s;
                    mma_bf16(acc[mt][nb], ah[mt], bh[s * 2], bh[s * 2 + 1]); // hh
                    mma_bf16(acc[mt][nb], ah[mt], bl[s * 2], bl[s * 2 + 1]); // hl
                    mma_bf16(acc[mt][nb], al[mt], bh[s * 2], bh[s * 2 + 1]); // lh
                }
        }
        if (t + 1 < KT) stageA(buf ^ 1);
        __syncthreads();
        buf ^= 1;
    }

    const int g = lane >> 2, t4 = lane & 3;

    // ---- C epilogue (fp16) ----
#pragma unroll
    for (int mt = 0; mt < 2; mt++)
#pragma unroll
        for (int nb = 0; nb < NBLK; nb++) {
            int r = row0 + wm * 32 + mt * 16 + g;
            int c = col0 + wn * WN + nb * 8 + 2 * t4;
            if (r < M)
                *reinterpret_cast<__half2*>(C + (size_t)r * N + c) =
                    __floats2half2_rn(acc[mt][nb][0], acc[mt][nb][1]);
            if (r + 8 < M)
                *reinterpret_cast<__half2*>(C + (size_t)(r + 8) * N + c) =
                    __floats2half2_rn(acc[mt][nb][2], acc[mt][nb][3]);
        }

    // ---- fused alpha epilogue ----
    float a0v[NBLK], a1v[NBLK], d0v[NBLK], d1v[NBLK];
#pragma unroll
    for (int nb = 0; nb < NBLK; nb++) {
        int cg = col0 + wn * WN + nb * 8 + 2 * t4;
        a0v[nb] = asrc[cg]; a1v[nb] = asrc[cg + 1];
        d0v[nb] = adst[cg]; d1v[nb] = adst[cg + 1];
    }
#pragma unroll
    for (int mt = 0; mt < 2; mt++) {
        float pas0 = 0.f, pad0 = 0.f, pas1 = 0.f, pad1 = 0.f;
#pragma unroll
        for (int nb = 0; nb < NBLK; nb++) {
            pas0 = fmaf(acc[mt][nb][0], a0v[nb], fmaf(acc[mt][nb][1], a1v[nb], pas0));
            pad0 = fmaf(acc[mt][nb][0], d0v[nb], fmaf(acc[mt][nb][1], d1v[nb], pad0));
            pas1 = fmaf(acc[mt][nb][2], a0v[nb], fmaf(acc[mt][nb][3], a1v[nb], pas1));
            pad1 = fmaf(acc[mt][nb][2], d0v[nb], fmaf(acc[mt][nb][3], d1v[nb], pad1));
        }
#pragma unroll
        for (int o = 1; o <= 2; o <<= 1) {
            pas0 += __shfl_xor_sync(0xFFFFFFFFu, pas0, o);
            pad0 += __shfl_xor_sync(0xFFFFFFFFu, pad0, o);
            pas1 += __shfl_xor_sync(0xFFFFFFFFu, pas1, o);
            pad1 += __shfl_xor_sync(0xFFFFFFFFu, pad1, o);
        }
        if (t4 == 0) {
            int rl = wm * 32 + mt * 16 + g;
            int r  = row0 + rl;
            if constexpr (AMODE == 1) {
                int h = (col0 >> 6) + wn;
                if (r < M)     { as_out[r * 4 + h] = pas0; ad_out[r * 4 + h] = pad0; }
                if (r + 8 < M) { as_out[(r + 8) * 4 + h] = pas1; ad_out[(r + 8) * 4 + h] = pad1; }
            } else {
                sAS[rl][wn] = pas0;     sAD[rl][wn] = pad0;
                sAS[rl + 8][wn] = pas1; sAD[rl + 8][wn] = pad1;
            }
        }
    }
    if constexpr (AMODE == 2) {
        __syncthreads();
        for (int rl = tid; rl < BM; rl += 256) {
            int r = row0 + rl;
            if (r < M) {
                as_out[r] = sAS[rl][0] + sAS[rl][1];
                ad_out[r] = sAD[rl][0] + sAD[rl][1];
            }
        }
    }
}

__global__ void __launch_bounds__(256, 2)
sgemm1_kernel(const float* __restrict__ x,
              const float* __restrict__ asrc, const float* __restrict__ adst,
              int M, int N, int K) {
    mma_gemm_body<128, 64, 1, 1>(x, nullptr, g_w1h, g_w1l, g_h1,
                                 asrc, adst, g_as1, g_ad1, M, N, K);
}

__global__ void __launch_bounds__(256, 2)
sgemm2_kernel(const float* __restrict__ asrc, const float* __restrict__ adst,
              int M, int N, int K) {
    mma_gemm_body<64, 32, 2, 0>(g_x2h, g_x2l, g_w2h, g_w2l, g_h2,
                                asrc, adst, g_as2, g_ad2, M, N, K);
}

// ---------------------------------------------------------------------------
// SINGLE-PASS per-node softmax + weighted aggregation, fp16 gathers.
// WPN warps cooperate on one node, splitting channels (WPN=2 for layer 1:
// halves per-warp latency exposure; traffic unchanged).
// out = (sum_e exp(e)*h[src_e]) / (sum_e exp(e) + 1e-16).
// ---------------------------------------------------------------------------
template <int H, int C, int WPN, bool RELU, bool BF16OUT>
__device__ __forceinline__ void aggregate_body(const __half* __restrict__ hfeat,
                                               const float* __restrict__ as_in,
                                               const float* __restrict__ ad_in,
                                               const float* __restrict__ bias,
                                               float* __restrict__ out,
                                               __nv_bfloat16* __restrict__ outh,
                                               __nv_bfloat16* __restrict__ outl,
                                               int Nn) {
    constexpr int HC  = H * C;
    constexpr int CPL = HC / (32 * WPN);  // 4 (layer1, WPN=2) or 2 (layer2)
    int gwarp = (blockIdx.x * blockDim.x + threadIdx.x) >> 5;
    int lane = threadIdx.x & 31;
    int n    = gwarp / WPN;
    int part = gwarp % WPN;
    if (n >= Nn) return;
    const int beg = g_rowptr[n];
    const int end = g_rowptr[n + 1];

    const int chan0 = part * (HC / WPN) + lane * CPL;
    const int headL = chan0 / C;
    const float adh = ad_in[n * H + headL];

    auto edge_w = [&](int s) -> float {
        float e = as_in[s * H + headL] + adh;
        e = (e > 0.f) ? e : 0.2f * e;
        return expf(e);
    };

    float acc[CPL];
#pragma unroll
    for (int k = 0; k < CPL; k++) acc[k] = 0.f;
    float denom = 0.f;

    int j = beg;
    for (; j + 7 < end; j += 8) {
        int   s[8];
        float a[8];
#pragma unroll
        for (int q = 0; q < 8; q++) s[q] = g_esrc[j + q];
        if constexpr (CPL == 4) {
            uint2 u[8];
#pragma unroll
            for (int q = 0; q < 8; q++)
                u[q] = *reinterpret_cast<const uint2*>(hfeat + (size_t)s[q] * HC + chan0);
#pragma unroll
            for (int q = 0; q < 8; q++) { a[q] = edge_w(s[q]); denom += a[q]; }
#pragma unroll
            for (int q = 0; q < 8; q++) {
                const __half2* p2 = reinterpret_cast<const __half2*>(&u[q]);
#pragma unroll
                for (int i = 0; i < 2; i++) {
                    float2 f = __half22float2(p2[i]);
                    acc[2 * i]     = fmaf(f.x, a[q], acc[2 * i]);
                    acc[2 * i + 1] = fmaf(f.y, a[q], acc[2 * i + 1]);
                }
            }
        } else {
            uint32_t u[8];
#pragma unroll
            for (int q = 0; q < 8; q++)
                u[q] = *reinterpret_cast<const uint32_t*>(hfeat + (size_t)s[q] * HC + chan0);
#pragma unroll
            for (int q = 0; q < 8; q++) { a[q] = edge_w(s[q]); denom += a[q]; }
#pragma unroll
            for (int q = 0; q < 8; q++) {
                float2 f = __half22float2(*reinterpret_cast<__half2*>(&u[q]));
                acc[0] = fmaf(f.x, a[q], acc[0]);
                acc[1] = fmaf(f.y, a[q], acc[1]);
            }
        }
    }
    for (; j < end; j++) {
        int s0 = g_esrc[j];
        float a0 = edge_w(s0);
        denom += a0;
        const __half* p0 = hfeat + (size_t)s0 * HC + chan0;
        if constexpr (CPL == 4) {
            uint2 u = *reinterpret_cast<const uint2*>(p0);
            const __half2* p2 = reinterpret_cast<const __half2*>(&u);
#pragma unroll
            for (int i = 0; i < 2; i++) {
                float2 f = __half22float2(p2[i]);
                acc[2 * i]     = fmaf(f.x, a0, acc[2 * i]);
                acc[2 * i + 1] = fmaf(f.y, a0, acc[2 * i + 1]);
            }
        } else {
            uint32_t u = *reinterpret_cast<const uint32_t*>(p0);
            float2 f = __half22float2(*reinterpret_cast<__half2*>(&u));
            acc[0] = fmaf(f.x, a0, acc[0]);
            acc[1] = fmaf(f.y, a0, acc[1]);
        }
    }

    const float inv = 1.0f / (denom + 1e-16f);
    float v[CPL];
#pragma unroll
    for (int k = 0; k < CPL; k++) {
        float w = fmaf(acc[k], inv, bias[chan0 + k]);
        if constexpr (RELU) w = fmaxf(w, 0.f);
        v[k] = w;
    }

    if constexpr (BF16OUT) {
        __nv_bfloat16 hb[CPL];
        float lof[CPL];
#pragma unroll
        for (int k = 0; k < CPL; k++) {
            hb[k] = __float2bfloat16(v[k]);
            lof[k] = v[k] - __bfloat162float(hb[k]);
        }
        uint2 uh, ul;
        {
            __nv_bfloat162 p0 = __halves2bfloat162(hb[0], hb[1]);
            __nv_bfloat162 p1 = __halves2bfloat162(hb[2], hb[3]);
            uh.x = *reinterpret_cast<uint32_t*>(&p0);
            uh.y = *reinterpret_cast<uint32_t*>(&p1);
        }
        {
            __nv_bfloat162 p0 = __floats2bfloat162_rn(lof[0], lof[1]);
            __nv_bfloat162 p1 = __floats2bfloat162_rn(lof[2], lof[3]);
            ul.x = *reinterpret_cast<uint32_t*>(&p0);
            ul.y = *reinterpret_cast<uint32_t*>(&p1);
        }
        *reinterpret_cast<uint2*>(outh + (size_t)n * HC + chan0) = uh;
        *reinterpret_cast<uint2*>(outl + (size_t)n * HC + chan0) = ul;
    } else {
        float* op = out + (size_t)n * HC + chan0;
#pragma unroll
        for (int k = 0; k < CPL; k++) op[k] = v[k];
    }
}

__global__ void agg1_kernel(const float* __restrict__ bias, int Nn) {
    aggregate_body<4, 64, 2, true, true>(g_h1, g_as1, g_ad1, bias,
                                         nullptr, g_x2h, g_x2l, Nn);
}

__global__ void agg2_kernel(const float* __restrict__ bias,
                            float* __restrict__ out, int Nn) {
    aggregate_body<1, 64, 1, false, false>(g_h2, g_as2, g_ad2, bias,
                                           out, nullptr, nullptr, Nn);
}

// ---------------------------------------------------------------------------
// kernel_launch — forked-stream DAG:
//   main: splitw -> sgemm1(x fused split + alpha1) -> [join CSR] agg1
//         -> sgemm2(+alpha2) -> agg2
//   side: zero -> count -> scan -> fill
// ---------------------------------------------------------------------------
extern "C" void kernel_launch(void* const* d_in, const int* in_sizes, int n_in,
                              void* d_out, int out_size) {
    const float* x      = (const float*)d_in[0];
    const int*   ei     = (const int*)d_in[1];     // int32 (JAX x64 disabled)
    const float* W1     = (const float*)d_in[2];
    const float* a_src1 = (const float*)d_in[3];
    const float* a_dst1 = (const float*)d_in[4];
    const float* b1     = (const float*)d_in[5];
    const float* W2     = (const float*)d_in[6];
    const float* a_src2 = (const float*)d_in[7];
    const float* a_dst2 = (const float*)d_in[8];
    const float* b2     = (const float*)d_in[9];

    const int C   = in_sizes[9];            // 64
    const int H   = in_sizes[3] / C;        // 4
    const int HC1 = H * C;                  // 256
    const int Fin = in_sizes[2] / HC1;      // 128
    const int Nn  = in_sizes[0] / Fin;      // 50000
    const int E   = in_sizes[1] / 2;        // 800000
    const int Etot = E + Nn;

    if (Nn > NMAX || Etot > EMAX || H != 4 || C != 64 || Fin != 128) return;

    cudaStream_t s1;
    cudaStreamCreateWithFlags(&s1, cudaStreamNonBlocking);
    cudaEvent_t evFork, evCsr;
    cudaEventCreateWithFlags(&evFork, cudaEventDisableTiming);
    cudaEventCreateWithFlags(&evCsr, cudaEventDisableTiming);

    cudaEventRecord(evFork, 0);
    cudaStreamWaitEvent(s1, evFork, 0);

    // ---- CSR build on side stream ----
    zero_deg_kernel<<<(Nn + 255) / 256, 256, 0, s1>>>(Nn);
    count_kernel<<<(Etot + 255) / 256, 256, 0, s1>>>(ei, E, Nn);
    scan_kernel<<<1, 1024, 0, s1>>>(Nn);

    // ---- main stream: weight split + GEMM1 (x split + alpha1 fused) ----
    {
        int total4 = (128 * 256 + 256 * 64) >> 2;
        splitw_kernel<<<(total4 + 255) / 256, 256>>>(W1, W2);
    }
    {
        dim3 grid(HC1 / 128, (Nn + 127) / 128);
        sgemm1_kernel<<<grid, 256>>>(x, a_src1, a_dst1, Nn, HC1, Fin);
    }

    fill_kernel<<<(Etot + 255) / 256, 256, 0, s1>>>(ei, E, Nn);
    cudaEventRecord(evCsr, s1);

    // join: agg1 needs CSR + h1 + alpha1
    cudaStreamWaitEvent(0, evCsr, 0);
    {
        int aggWarps = Nn * 2;                     // 2 warps per node
        agg1_kernel<<<(aggWarps + 7) / 8, 256>>>(b1, Nn);
    }

    // ---- layer 2 (alpha2 fused into sgemm2) ----
    {
        dim3 grid(C / 64, (Nn + 127) / 128);
        sgemm2_kernel<<<grid, 256>>>(a_src2, a_dst2, Nn, C, HC1);
    }
    agg2_kernel<<<(Nn + 7) / 8, 256>>>(b2, (float*)d_out, Nn);
}

// round 17
// speedup vs baseline: 1.2281x; 1.2281x over previous
#include <cuda_runtime.h>
#include <cuda_bf16.h>
#include <cuda_fp16.h>
#include <math.h>
#include <stdint.h>

// ---------------------------------------------------------------------------
// Static device scratch (no allocations allowed anywhere).
// Instance: N=50000, E=800000 (+N self loops), Fin=128, H=4, C=64.
// ---------------------------------------------------------------------------
#define NMAX 65536
#define EMAX 2200000

__device__ __half g_h1[(size_t)NMAX * 256];        // layer-1 features (fp16)
__device__ __half g_h2[(size_t)NMAX * 64];         // layer-2 features (fp16)
__device__ __nv_bfloat16 g_xh[(size_t)NMAX * 128]; // x split hi
__device__ __nv_bfloat16 g_xl[(size_t)NMAX * 128]; // x split lo
__device__ __nv_bfloat16 g_x2h[(size_t)NMAX * 256];// relu(agg1+b1) split hi
__device__ __nv_bfloat16 g_x2l[(size_t)NMAX * 256];// relu(agg1+b1) split lo
__device__ __nv_bfloat16 g_w1h[128 * 256], g_w1l[128 * 256];
__device__ __nv_bfloat16 g_w2h[256 * 64],  g_w2l[256 * 64];
__device__ float g_as1[NMAX * 4];
__device__ float g_ad1[NMAX * 4];
__device__ float g_as2[NMAX];
__device__ float g_ad2[NMAX];
__device__ int   g_deg[NMAX];
__device__ int   g_pos[NMAX];
__device__ int   g_rowptr[NMAX + 1];
__device__ int   g_esrc[EMAX];

// ---------------------------------------------------------------------------
// CSR construction (counting sort by destination). edge_index is INT32.
// ---------------------------------------------------------------------------
__global__ void zero_deg_kernel(int Nn) {
    int i = blockIdx.x * blockDim.x + threadIdx.x;
    if (i < Nn) g_deg[i] = 0;
}

__global__ void count_kernel(const int* __restrict__ ei, int E, int Nn) {
    int i = blockIdx.x * blockDim.x + threadIdx.x;
    int tot = E + Nn;
    if (i >= tot) return;
    int d = (i < E) ? ei[E + i] : (i - E);
    if ((unsigned)d < (unsigned)Nn) atomicAdd(&g_deg[d], 1);
}

__global__ void scan_kernel(int N) {
    __shared__ int ssum[1024];
    int tid = threadIdx.x;
    int chunk = (N + 1023) >> 10;
    int start = tid * chunk;
    int end = min(start + chunk, N);
    int s = 0;
    for (int i = start; i < end; i++) s += g_deg[i];
    ssum[tid] = s;
    __syncthreads();
    for (int off = 1; off < 1024; off <<= 1) {
        int v = (tid >= off) ? ssum[tid - off] : 0;
        __syncthreads();
        ssum[tid] += v;
        __syncthreads();
    }
    int run = (tid > 0) ? ssum[tid - 1] : 0;
    for (int i = start; i < end; i++) {
        g_rowptr[i] = run;
        g_pos[i] = run;
        run += g_deg[i];
    }
    if (start < N && end == N) g_rowptr[N] = run;
}

__global__ void fill_kernel(const int* __restrict__ ei, int E, int Nn) {
    int i = blockIdx.x * blockDim.x + threadIdx.x;
    int tot = E + Nn;
    if (i >= tot) return;
    int s, d;
    if (i < E) { s = ei[i]; d = ei[E + i]; }
    else       { s = d = i - E; }
    if ((unsigned)d >= (unsigned)Nn || (unsigned)s >= (unsigned)Nn) return;
    int slot = atomicAdd(&g_pos[d], 1);
    g_esrc[slot] = s;
}

// ---------------------------------------------------------------------------
// fp32 -> (bf16 hi, bf16 lo) split, vectorized: 4 floats / thread.
// Covers x, W1, W2 (proven R14/R15 form).
// ---------------------------------------------------------------------------
__global__ void split3_kernel(const float* __restrict__ x,
                              const float* __restrict__ W1,
                              const float* __restrict__ W2, int nx) {
    const int NW1 = 128 * 256, NW2 = 256 * 64;
    int total4 = (nx + NW1 + NW2) >> 2;
    for (int i = blockIdx.x * blockDim.x + threadIdx.x; i < total4;
         i += gridDim.x * blockDim.x) {
        int base = i << 2;
        const float* src;
        __nv_bfloat16 *dh, *dl;
        if (base < nx)            { src = x + base;          dh = g_xh + base;  dl = g_xl + base; }
        else if (base < nx + NW1) { int o = base - nx;       src = W1 + o; dh = g_w1h + o; dl = g_w1l + o; }
        else                      { int o = base - nx - NW1; src = W2 + o; dh = g_w2h + o; dl = g_w2l + o; }
        float4 v = *reinterpret_cast<const float4*>(src);
        __nv_bfloat16 h0 = __float2bfloat16(v.x), h1 = __float2bfloat16(v.y);
        __nv_bfloat16 h2 = __float2bfloat16(v.z), h3 = __float2bfloat16(v.w);
        __nv_bfloat162 hh0 = __halves2bfloat162(h0, h1);
        __nv_bfloat162 hh1 = __halves2bfloat162(h2, h3);
        __nv_bfloat162 ll0 = __floats2bfloat162_rn(v.x - __bfloat162float(h0),
                                                   v.y - __bfloat162float(h1));
        __nv_bfloat162 ll1 = __floats2bfloat162_rn(v.z - __bfloat162float(h2),
                                                   v.w - __bfloat162float(h3));
        uint2 uh, ul;
        uh.x = *reinterpret_cast<uint32_t*>(&hh0);
        uh.y = *reinterpret_cast<uint32_t*>(&hh1);
        ul.x = *reinterpret_cast<uint32_t*>(&ll0);
        ul.y = *reinterpret_cast<uint32_t*>(&ll1);
        *reinterpret_cast<uint2*>(dh) = uh;
        *reinterpret_cast<uint2*>(dl) = ul;
    }
}

// ---------------------------------------------------------------------------
// bf16 tensor-core GEMM (3-term split), fp16 output, fused alpha epilogue.
// (Exactly the proven 248us round-15 configuration: cp.async staging only.)
// AMODE=1 (GEMM1): warp's 64-col span = one head -> direct alpha store.
// AMODE=2 (GEMM2, H=1): two column-warps combine via smem.
// ---------------------------------------------------------------------------
__device__ __forceinline__ void ldsm_x4(uint32_t r[4], uint32_t addr) {
    asm volatile("ldmatrix.sync.aligned.m8n8.x4.shared.b16 {%0,%1,%2,%3}, [%4];"
                 : "=r"(r[0]), "=r"(r[1]), "=r"(r[2]), "=r"(r[3]) : "r"(addr));
}
__device__ __forceinline__ void ldsm_x4_t(uint32_t r[4], uint32_t addr) {
    asm volatile("ldmatrix.sync.aligned.m8n8.x4.trans.shared.b16 {%0,%1,%2,%3}, [%4];"
                 : "=r"(r[0]), "=r"(r[1]), "=r"(r[2]), "=r"(r[3]) : "r"(addr));
}
__device__ __forceinline__ void mma_bf16(float c[4], const uint32_t a[4],
                                         uint32_t b0, uint32_t b1) {
    asm volatile(
        "mma.sync.aligned.m16n8k16.row.col.f32.bf16.bf16.f32 "
        "{%0,%1,%2,%3}, {%4,%5,%6,%7}, {%8,%9}, {%0,%1,%2,%3};\n"
        : "+f"(c[0]), "+f"(c[1]), "+f"(c[2]), "+f"(c[3])
        : "r"(a[0]), "r"(a[1]), "r"(a[2]), "r"(a[3]), "r"(b0), "r"(b1));
}
__device__ __forceinline__ void cp16(uint32_t dst, const void* src, int sz) {
    asm volatile("cp.async.cg.shared.global [%0], [%1], 16, %2;"
                 :: "r"(dst), "l"(src), "r"(sz));
}
#define CP_COMMIT() asm volatile("cp.async.commit_group;" ::: "memory")
#define CP_WAIT0()  asm volatile("cp.async.wait_group 0;" ::: "memory")

template <int BN, int WN, int AMODE>
__device__ __forceinline__ void mma_gemm_body(const __nv_bfloat16* __restrict__ Ah,
                                              const __nv_bfloat16* __restrict__ Al,
                                              const __nv_bfloat16* __restrict__ Bh,
                                              const __nv_bfloat16* __restrict__ Bl,
                                              __half* __restrict__ C,
                                              const float* __restrict__ asrc,
                                              const float* __restrict__ adst,
                                              float* __restrict__ as_out,
                                              float* __restrict__ ad_out,
                                              int M, int N, int K) {
    constexpr int BM  = 128;
    constexpr int NIC = BN / 8;
    constexpr int NP  = WN / 16;
    constexpr int NBLK = WN / 8;

    __shared__ uint4 sAh[2][256], sAl[2][256];
    __shared__ uint4 sBh[2][BN * 2], sBl[2][BN * 2];
    __shared__ float sAS[BM][2], sAD[BM][2];   // AMODE==2 combine buffer

    const int tid    = threadIdx.x;
    const int warpId = tid >> 5;
    const int lane   = tid & 31;
    const int row0 = blockIdx.y * BM;
    const int col0 = blockIdx.x * BN;

    const int aki = tid >> 7, ami = (tid >> 3) & 15, arow = tid & 7;
    const int aRowG = row0 + ami * 8 + arow;
    const int aDst  = (ami * 2 + aki) * 8 + arow;
    const int aszv  = (aRowG < M) ? 16 : 0;

    const bool bAct = (tid < BN * 2);
    const int bki  = tid / (NIC * 8);
    const int brem = tid % (NIC * 8);
    const int bni  = brem >> 3, brow = brem & 7;
    const int bDst = (bni * 2 + bki) * 8 + brow;
    const int bColG = col0 + bni * 8;

    uint32_t baseAh[2] = {(uint32_t)__cvta_generic_to_shared(&sAh[0][0]),
                          (uint32_t)__cvta_generic_to_shared(&sAh[1][0])};
    uint32_t baseAl[2] = {(uint32_t)__cvta_generic_to_shared(&sAl[0][0]),
                          (uint32_t)__cvta_generic_to_shared(&sAl[1][0])};
    uint32_t baseBh[2] = {(uint32_t)__cvta_generic_to_shared(&sBh[0][0]),
                          (uint32_t)__cvta_generic_to_shared(&sBh[1][0])};
    uint32_t baseBl[2] = {(uint32_t)__cvta_generic_to_shared(&sBl[0][0]),
                          (uint32_t)__cvta_generic_to_shared(&sBl[1][0])};

    auto loadTile = [&](int k0, int buf) {
        cp16(baseAh[buf] + aDst * 16, Ah + (size_t)aRowG * K + k0 + aki * 8, aszv);
        cp16(baseAl[buf] + aDst * 16, Al + (size_t)aRowG * K + k0 + aki * 8, aszv);
        if (bAct) {
            int kk = k0 + bki * 8 + brow;
            cp16(baseBh[buf] + bDst * 16, Bh + (size_t)kk * N + bColG, 16);
            cp16(baseBl[buf] + bDst * 16, Bl + (size_t)kk * N + bColG, 16);
        }
        CP_COMMIT();
    };

    const int wm = warpId & 3;
    const int wn = warpId >> 2;
    const int mi0 = wm * 4;
    const int ni0 = wn * (WN / 8);
    const int q = lane >> 3, r8 = lane & 7;
    uint32_t aoff[2], boff[NP];
#pragma unroll
    for (int mt = 0; mt < 2; mt++)
        aoff[mt] = ((mi0 + mt * 2 + (q & 1)) * 2 + (q >> 1)) * 128 + r8 * 16;
#pragma unroll
    for (int np = 0; np < NP; np++)
        boff[np] = ((ni0 + np * 2 + (q >> 1)) * 2 + (q & 1)) * 128 + r8 * 16;

    float acc[2][NBLK][4];
#pragma unroll
    for (int mt = 0; mt < 2; mt++)
#pragma unroll
        for (int nb = 0; nb < NBLK; nb++)
#pragma unroll
            for (int e = 0; e < 4; e++) acc[mt][nb][e] = 0.f;

    const int KT = K >> 4;
    loadTile(0, 0);
    int buf = 0;
    for (int t = 0; t < KT; t++) {
        CP_WAIT0();
        __syncthreads();
        if (t + 1 < KT) loadTile((t + 1) << 4, buf ^ 1);

        uint32_t ah[2][4], al[2][4];
#pragma unroll
        for (int mt = 0; mt < 2; mt++) {
            ldsm_x4(ah[mt], baseAh[buf] + aoff[mt]);
            ldsm_x4(al[mt], baseAl[buf] + aoff[mt]);
        }
#pragma unroll
        for (int np = 0; np < NP; np++) {
            uint32_t bh[4], bl[4];
            ldsm_x4_t(bh, baseBh[buf] + boff[np]);
            ldsm_x4_t(bl, baseBl[buf] + boff[np]);
#pragma unroll
            for (int mt = 0; mt < 2; mt++)
#pragma unroll
                for (int s = 0; s < 2; s++) {
                    int nb = np * 2 + s;
                    mma_bf16(acc[mt][nb], ah[mt], bh[s * 2], bh[s * 2 + 1]); // hh
                    mma_bf16(acc[mt][nb], ah[mt], bl[s * 2], bl[s * 2 + 1]); // hl
                    mma_bf16(acc[mt][nb], al[mt], bh[s * 2], bh[s * 2 + 1]); // lh
                }
        }
        __syncthreads();
        buf ^= 1;
    }

    const int g = lane >> 2, t4 = lane & 3;

    // ---- C epilogue (fp16) ----
#pragma unroll
    for (int mt = 0; mt < 2; mt++)
#pragma unroll
        for (int nb = 0; nb < NBLK; nb++) {
            int r = row0 + wm * 32 + mt * 16 + g;
            int c = col0 + wn * WN + nb * 8 + 2 * t4;
            if (r < M)
                *reinterpret_cast<__half2*>(C + (size_t)r * N + c) =
                    __floats2half2_rn(acc[mt][nb][0], acc[mt][nb][1]);
            if (r + 8 < M)
                *reinterpret_cast<__half2*>(C + (size_t)(r + 8) * N + c) =
                    __floats2half2_rn(acc[mt][nb][2], acc[mt][nb][3]);
        }

    // ---- fused alpha epilogue ----
    float a0v[NBLK], a1v[NBLK], d0v[NBLK], d1v[NBLK];
#pragma unroll
    for (int nb = 0; nb < NBLK; nb++) {
        int cg = col0 + wn * WN + nb * 8 + 2 * t4;
        a0v[nb] = asrc[cg]; a1v[nb] = asrc[cg + 1];
        d0v[nb] = adst[cg]; d1v[nb] = adst[cg + 1];
    }
#pragma unroll
    for (int mt = 0; mt < 2; mt++) {
        float pas0 = 0.f, pad0 = 0.f, pas1 = 0.f, pad1 = 0.f;
#pragma unroll
        for (int nb = 0; nb < NBLK; nb++) {
            pas0 = fmaf(acc[mt][nb][0], a0v[nb], fmaf(acc[mt][nb][1], a1v[nb], pas0));
            pad0 = fmaf(acc[mt][nb][0], d0v[nb], fmaf(acc[mt][nb][1], d1v[nb], pad0));
            pas1 = fmaf(acc[mt][nb][2], a0v[nb], fmaf(acc[mt][nb][3], a1v[nb], pas1));
            pad1 = fmaf(acc[mt][nb][2], d0v[nb], fmaf(acc[mt][nb][3], d1v[nb], pad1));
        }
#pragma unroll
        for (int o = 1; o <= 2; o <<= 1) {
            pas0 += __shfl_xor_sync(0xFFFFFFFFu, pas0, o);
            pad0 += __shfl_xor_sync(0xFFFFFFFFu, pad0, o);
            pas1 += __shfl_xor_sync(0xFFFFFFFFu, pas1, o);
            pad1 += __shfl_xor_sync(0xFFFFFFFFu, pad1, o);
        }
        if (t4 == 0) {
            int rl = wm * 32 + mt * 16 + g;
            int r  = row0 + rl;
            if constexpr (AMODE == 1) {
                int h = (col0 >> 6) + wn;
                if (r < M)     { as_out[r * 4 + h] = pas0; ad_out[r * 4 + h] = pad0; }
                if (r + 8 < M) { as_out[(r + 8) * 4 + h] = pas1; ad_out[(r + 8) * 4 + h] = pad1; }
            } else {
                sAS[rl][wn] = pas0;     sAD[rl][wn] = pad0;
                sAS[rl + 8][wn] = pas1; sAD[rl + 8][wn] = pad1;
            }
        }
    }
    if constexpr (AMODE == 2) {
        __syncthreads();
        for (int rl = tid; rl < BM; rl += 256) {
            int r = row0 + rl;
            if (r < M) {
                as_out[r] = sAS[rl][0] + sAS[rl][1];
                ad_out[r] = sAD[rl][0] + sAD[rl][1];
            }
        }
    }
}

__global__ void __launch_bounds__(256, 2)
sgemm1_kernel(const float* __restrict__ asrc, const float* __restrict__ adst,
              int M, int N, int K) {
    mma_gemm_body<128, 64, 1>(g_xh, g_xl, g_w1h, g_w1l, g_h1,
                              asrc, adst, g_as1, g_ad1, M, N, K);
}

__global__ void __launch_bounds__(256, 2)
sgemm2_kernel(const float* __restrict__ asrc, const float* __restrict__ adst,
              int M, int N, int K) {
    mma_gemm_body<64, 32, 2>(g_x2h, g_x2l, g_w2h, g_w2l, g_h2,
                             asrc, adst, g_as2, g_ad2, M, N, K);
}

// ---------------------------------------------------------------------------
// SINGLE-PASS per-node softmax + weighted aggregation, fp16 gathers.
// WPN warps cooperate on one node, splitting channels (WPN=2 for layer 1:
// halves per-warp latency exposure; feature traffic unchanged).
// out = (sum_e exp(e)*h[src_e]) / (sum_e exp(e) + 1e-16).
// ---------------------------------------------------------------------------
template <int H, int C, int WPN, bool RELU, bool BF16OUT>
__device__ __forceinline__ void aggregate_body(const __half* __restrict__ hfeat,
                                               const float* __restrict__ as_in,
                                               const float* __restrict__ ad_in,
                                               const float* __restrict__ bias,
                                               float* __restrict__ out,
                                               __nv_bfloat16* __restrict__ outh,
                                               __nv_bfloat16* __restrict__ outl,
                                               int Nn) {
    constexpr int HC  = H * C;
    constexpr int CPL = HC / (32 * WPN);  // 4 (layer1, WPN=2) or 2 (layer2)
    int gwarp = (blockIdx.x * blockDim.x + threadIdx.x) >> 5;
    int lane = threadIdx.x & 31;
    int n    = gwarp / WPN;
    int part = gwarp % WPN;
    if (n >= Nn) return;
    const int beg = g_rowptr[n];
    const int end = g_rowptr[n + 1];

    const int chan0 = part * (HC / WPN) + lane * CPL;
    const int headL = chan0 / C;
    const float adh = ad_in[n * H + headL];

    auto edge_w = [&](int s) -> float {
        float e = as_in[s * H + headL] + adh;
        e = (e > 0.f) ? e : 0.2f * e;
        return __expf(e);                       // fast exp; |e| bounded, 2^-21 rel
    };

    float acc[CPL];
#pragma unroll
    for (int k = 0; k < CPL; k++) acc[k] = 0.f;
    float denom = 0.f;

    int j = beg;
    for (; j + 7 < end; j += 8) {
        int   s[8];
        float a[8];
#pragma unroll
        for (int q = 0; q < 8; q++) s[q] = g_esrc[j + q];
        if constexpr (CPL == 4) {
            uint2 u[8];
#pragma unroll
            for (int q = 0; q < 8; q++)
                u[q] = *reinterpret_cast<const uint2*>(hfeat + (size_t)s[q] * HC + chan0);
#pragma unroll
            for (int q = 0; q < 8; q++) { a[q] = edge_w(s[q]); denom += a[q]; }
#pragma unroll
            for (int q = 0; q < 8; q++) {
                const __half2* p2 = reinterpret_cast<const __half2*>(&u[q]);
#pragma unroll
                for (int i = 0; i < 2; i++) {
                    float2 f = __half22float2(p2[i]);
                    acc[2 * i]     = fmaf(f.x, a[q], acc[2 * i]);
                    acc[2 * i + 1] = fmaf(f.y, a[q], acc[2 * i + 1]);
                }
            }
        } else {
            uint32_t u[8];
#pragma unroll
            for (int q = 0; q < 8; q++)
                u[q] = *reinterpret_cast<const uint32_t*>(hfeat + (size_t)s[q] * HC + chan0);
#pragma unroll
            for (int q = 0; q < 8; q++) { a[q] = edge_w(s[q]); denom += a[q]; }
#pragma unroll
            for (int q = 0; q < 8; q++) {
                float2 f = __half22float2(*reinterpret_cast<__half2*>(&u[q]));
                acc[0] = fmaf(f.x, a[q], acc[0]);
                acc[1] = fmaf(f.y, a[q], acc[1]);
            }
        }
    }
    for (; j < end; j++) {
        int s0 = g_esrc[j];
        float a0 = edge_w(s0);
        denom += a0;
        const __half* p0 = hfeat + (size_t)s0 * HC + chan0;
        if constexpr (CPL == 4) {
            uint2 u = *reinterpret_cast<const uint2*>(p0);
            const __half2* p2 = reinterpret_cast<const __half2*>(&u);
#pragma unroll
            for (int i = 0; i < 2; i++) {
                float2 f = __half22float2(p2[i]);
                acc[2 * i]     = fmaf(f.x, a0, acc[2 * i]);
                acc[2 * i + 1] = fmaf(f.y, a0, acc[2 * i + 1]);
            }
        } else {
            uint32_t u = *reinterpret_cast<const uint32_t*>(p0);
            float2 f = __half22float2(*reinterpret_cast<__half2*>(&u));
            acc[0] = fmaf(f.x, a0, acc[0]);
            acc[1] = fmaf(f.y, a0, acc[1]);
        }
    }

    const float inv = 1.0f / (denom + 1e-16f);
    float v[CPL];
#pragma unroll
    for (int k = 0; k < CPL; k++) {
        float w = fmaf(acc[k], inv, bias[chan0 + k]);
        if constexpr (RELU) w = fmaxf(w, 0.f);
        v[k] = w;
    }

    if constexpr (BF16OUT) {
        __nv_bfloat16 hb[CPL];
        float lof[CPL];
#pragma unroll
        for (int k = 0; k < CPL; k++) {
            hb[k] = __float2bfloat16(v[k]);
            lof[k] = v[k] - __bfloat162float(hb[k]);
        }
        uint2 uh, ul;
        {
            __nv_bfloat162 p0 = __halves2bfloat162(hb[0], hb[1]);
            __nv_bfloat162 p1 = __halves2bfloat162(hb[2], hb[3]);
            uh.x = *reinterpret_cast<uint32_t*>(&p0);
            uh.y = *reinterpret_cast<uint32_t*>(&p1);
        }
        {
            __nv_bfloat162 p0 = __floats2bfloat162_rn(lof[0], lof[1]);
            __nv_bfloat162 p1 = __floats2bfloat162_rn(lof[2], lof[3]);
            ul.x = *reinterpret_cast<uint32_t*>(&p0);
            ul.y = *reinterpret_cast<uint32_t*>(&p1);
        }
        *reinterpret_cast<uint2*>(outh + (size_t)n * HC + chan0) = uh;
        *reinterpret_cast<uint2*>(outl + (size_t)n * HC + chan0) = ul;
    } else {
        float* op = out + (size_t)n * HC + chan0;
#pragma unroll
        for (int k = 0; k < CPL; k++) op[k] = v[k];
    }
}

__global__ void agg1_kernel(const float* __restrict__ bias, int Nn) {
    aggregate_body<4, 64, 2, true, true>(g_h1, g_as1, g_ad1, bias,
                                         nullptr, g_x2h, g_x2l, Nn);
}

__global__ void agg2_kernel(const float* __restrict__ bias,
                            float* __restrict__ out, int Nn) {
    aggregate_body<1, 64, 1, false, false>(g_h2, g_as2, g_ad2, bias,
                                           out, nullptr, nullptr, Nn);
}

// ---------------------------------------------------------------------------
// kernel_launch — forked-stream DAG:
//   main: split3 -> sgemm1(+alpha1) -> [join CSR] agg1 -> sgemm2(+alpha2) -> agg2
//   side: zero -> count -> scan -> fill
// ---------------------------------------------------------------------------
extern "C" void kernel_launch(void* const* d_in, const int* in_sizes, int n_in,
                              void* d_out, int out_size) {
    const float* x      = (const float*)d_in[0];
    const int*   ei     = (const int*)d_in[1];     // int32 (JAX x64 disabled)
    const float* W1     = (const float*)d_in[2];
    const float* a_src1 = (const float*)d_in[3];
    const float* a_dst1 = (const float*)d_in[4];
    const float* b1     = (const float*)d_in[5];
    const float* W2     = (const float*)d_in[6];
    const float* a_src2 = (const float*)d_in[7];
    const float* a_dst2 = (const float*)d_in[8];
    const float* b2     = (const float*)d_in[9];

    const int C   = in_sizes[9];            // 64
    const int H   = in_sizes[3] / C;        // 4
    const int HC1 = H * C;                  // 256
    const int Fin = in_sizes[2] / HC1;      // 128
    const int Nn  = in_sizes[0] / Fin;      // 50000
    const int E   = in_sizes[1] / 2;        // 800000
    const int Etot = E + Nn;

    if (Nn > NMAX || Etot > EMAX || H != 4 || C != 64 || Fin != 128) return;

    cudaStream_t s1;
    cudaStreamCreateWithFlags(&s1, cudaStreamNonBlocking);
    cudaEvent_t evFork, evCsr;
    cudaEventCreateWithFlags(&evFork, cudaEventDisableTiming);
    cudaEventCreateWithFlags(&evCsr, cudaEventDisableTiming);

    cudaEventRecord(evFork, 0);
    cudaStreamWaitEvent(s1, evFork, 0);

    // ---- CSR build on side stream ----
    zero_deg_kernel<<<(Nn + 255) / 256, 256, 0, s1>>>(Nn);
    count_kernel<<<(Etot + 255) / 256, 256, 0, s1>>>(ei, E, Nn);
    scan_kernel<<<1, 1024, 0, s1>>>(Nn);

    // ---- main stream: split + GEMM1 (alpha1 fused) ----
    {
        int nx = Nn * Fin;
        int total4 = (nx + 128 * 256 + 256 * 64) >> 2;
        split3_kernel<<<(total4 + 255) / 256, 256>>>(x, W1, W2, nx);
    }
    {
        dim3 grid(HC1 / 128, (Nn + 127) / 128);
        sgemm1_kernel<<<grid, 256>>>(a_src1, a_dst1, Nn, HC1, Fin);
    }

    fill_kernel<<<(Etot + 255) / 256, 256, 0, s1>>>(ei, E, Nn);
    cudaEventRecord(evCsr, s1);

    // join: agg1 needs CSR + h1 + alpha1
    cudaStreamWaitEvent(0, evCsr, 0);
    {
        int aggWarps = Nn * 2;                     // 2 warps per node
        agg1_kernel<<<(aggWarps + 7) / 8, 256>>>(b1, Nn);
    }

    // ---- layer 2 (alpha2 fused into sgemm2) ----
    {
        dim3 grid(C / 64, (Nn + 127) / 128);
        sgemm2_kernel<<<grid, 256>>>(a_src2, a_dst2, Nn, C, HC1);
    }
    agg2_kernel<<<(Nn + 7) / 8, 256>>>(b2, (float*)d_out, Nn);
}